// round 10
// baseline (speedup 1.0000x reference)
#include <cuda_runtime.h>
#include <cuda_bf16.h>
#include <cstdint>

#define NUM_EXPERTS 16
#define Z_LOSS 1e-3f
#define ALPHA (1.0f / 1000.0f)

#define GRID 152                 // one block per SM on GB300 (152 SMs)
#define NTHREADS 256
#define TILE_BYTES 16384
#define TILE_F4 (TILE_BYTES / 16)        // 1024 float4 per tile
#define NSTAGES 2                        // 32KB ring: fits 48KB limit w/ static smem
#define N_TILES 8192                     // 134217728 B / 16384 B exactly
#define SMEM_BYTES (NSTAGES * TILE_BYTES)

__device__ float g_partials[GRID];
__device__ int g_ticket = 0;   // reset by the last block each launch

__device__ __forceinline__ uint32_t smem_u32(const void* p) {
    uint32_t a;
    asm("{ .reg .u64 t; cvta.to.shared.u64 t, %1; cvt.u32.u64 %0, t; }"
        : "=r"(a) : "l"(p));
    return a;
}

__device__ __forceinline__ void mbar_init(uint32_t mba, uint32_t count) {
    asm volatile("mbarrier.init.shared.b64 [%0], %1;" :: "r"(mba), "r"(count) : "memory");
}

__device__ __forceinline__ void bulk_load(uint32_t dst, const char* src, uint32_t mba) {
    asm volatile("mbarrier.arrive.expect_tx.shared::cta.b64 _, [%0], %1;"
                 :: "r"(mba), "r"((uint32_t)TILE_BYTES) : "memory");
    asm volatile("cp.async.bulk.shared::cta.global.mbarrier::complete_tx::bytes "
                 "[%0], [%1], %2, [%3];"
                 :: "r"(dst), "l"(src), "r"((uint32_t)TILE_BYTES), "r"(mba) : "memory");
}

__device__ __forceinline__ void mbar_wait(uint32_t mba, uint32_t parity) {
    asm volatile(
        "{\n\t"
        ".reg .pred P;\n\t"
        "WL_%=:\n\t"
        "mbarrier.try_wait.parity.acquire.cta.shared::cta.b64 P, [%0], %1, 0x989680;\n\t"
        "@P bra.uni WD_%=;\n\t"
        "bra.uni WL_%=;\n\t"
        "WD_%=:\n\t"
        "}"
        :: "r"(mba), "r"(parity) : "memory");
}

__global__ __launch_bounds__(NTHREADS) void router_kernel(
    const char* __restrict__ x,
    const float* __restrict__ prototypes,
    const float* __restrict__ usage_ema,
    float* __restrict__ out, int out_size, float inv_n)
{
    extern __shared__ __align__(128) char smem_raw[];
    float4* smem = (float4*)smem_raw;
    __shared__ __align__(8) uint64_t mbar[NSTAGES];
    __shared__ float sdata[NTHREADS / 32];
    __shared__ bool is_last;

    const int tid = threadIdx.x;
    const int bid = blockIdx.x;
    // 8192 = 152*53 + 136 : blocks 0..135 process 54 tiles, rest 53
    const int my_tiles = (N_TILES / GRID) + (bid < (N_TILES % GRID) ? 1 : 0);

    if (tid == 0) {
#pragma unroll
        for (int s = 0; s < NSTAGES; s++)
            mbar_init(smem_u32(&mbar[s]), 1);
    }
    __syncthreads();

    // prologue: fill the pipeline
    if (tid == 0) {
#pragma unroll
        for (int s = 0; s < NSTAGES; s++) {
            if (s < my_tiles) {
                const char* src = x + (size_t)(bid + s * GRID) * TILE_BYTES;
                bulk_load(smem_u32(smem_raw) + s * TILE_BYTES, src, smem_u32(&mbar[s]));
            }
        }
    }

    // main loop: wait -> reduce from smem -> sync -> refill stage
    float s0 = 0.f, s1 = 0.f, s2 = 0.f, s3 = 0.f;
    for (int i = 0; i < my_tiles; i++) {
        const int stage = i % NSTAGES;
        const uint32_t parity = (uint32_t)((i / NSTAGES) & 1);
        mbar_wait(smem_u32(&mbar[stage]), parity);

        const float4* t = smem + stage * TILE_F4;
#pragma unroll
        for (int k = 0; k < TILE_F4 / NTHREADS; k++) {   // 4 x LDS.128
            float4 v = t[tid + k * NTHREADS];
            s0 += v.x; s1 += v.y; s2 += v.z; s3 += v.w;
        }
        __syncthreads();   // all threads consumed this stage

        if (tid == 0 && (i + NSTAGES) < my_tiles) {
            const char* src = x + (size_t)(bid + (i + NSTAGES) * GRID) * TILE_BYTES;
            bulk_load(smem_u32(smem_raw) + stage * TILE_BYTES, src, smem_u32(&mbar[stage]));
        }
    }
    float s = (s0 + s1) + (s2 + s3);

    // block reduce
#pragma unroll
    for (int off = 16; off > 0; off >>= 1)
        s += __shfl_down_sync(0xffffffffu, s, off);
    if ((tid & 31) == 0) sdata[tid >> 5] = s;
    __syncthreads();
    if (tid < 32) {
        float v = (tid < NTHREADS / 32) ? sdata[tid] : 0.f;
#pragma unroll
        for (int off = 4; off > 0; off >>= 1)
            v += __shfl_down_sync(0xffffffffu, v, off);
        if (tid == 0) {
            g_partials[bid] = v;
            __threadfence();
            int old = atomicAdd(&g_ticket, 1);
            is_last = (old == GRID - 1);
        }
    }
    __syncthreads();
    if (!is_last) return;

    // ---- tail (last block): reduce 152 partials + epilogue ----
    float t = (tid < GRID) ? __ldcg(&g_partials[tid]) : 0.f;
#pragma unroll
    for (int off = 16; off > 0; off >>= 1)
        t += __shfl_down_sync(0xffffffffu, t, off);
    if ((tid & 31) == 0) sdata[tid >> 5] = t;

    // initialize every output element (d_out is poisoned with 0xAA)
    for (int i = tid; i < out_size; i += NTHREADS) out[i] = 0.0f;
    __syncthreads();

    if (tid == 0) {
        float tot = 0.f;
#pragma unroll
        for (int i = 0; i < NTHREADS / 32; i++) tot += sdata[i];
        float xm = tot * inv_n;

        float sim[NUM_EXPERTS];
        float mx = -3.4e38f;
#pragma unroll
        for (int e = 0; e < NUM_EXPERTS; e++) {
            float dd = prototypes[e] - xm;
            sim[e] = -dd * dd;
            if (sim[e] > mx) mx = sim[e];
        }
        float probs[NUM_EXPERTS];
        float denom = 0.f;
#pragma unroll
        for (int e = 0; e < NUM_EXPERTS; e++) {
            probs[e] = expf(sim[e] - mx);
            denom += probs[e];
        }
        float inv_denom = 1.0f / denom;
#pragma unroll
        for (int e = 0; e < NUM_EXPERTS; e++) probs[e] *= inv_denom;

        // stable top-2 (ties -> lowest index, matching jax.lax.top_k)
        int i0 = 0;
        for (int e = 1; e < NUM_EXPERTS; e++)
            if (probs[e] > probs[i0]) i0 = e;
        int i1 = (i0 == 0) ? 1 : 0;
        for (int e = 0; e < NUM_EXPERTS; e++) {
            if (e == i0) continue;
            if (probs[e] > probs[i1]) i1 = e;
        }

        float mask[NUM_EXPERTS];
#pragma unroll
        for (int e = 0; e < NUM_EXPERTS; e++) mask[e] = 0.f;
        mask[i0] = 1.f; mask[i1] = 1.f;

        const float target = 1.0f / NUM_EXPERTS;
        float acc = 0.f;
        float ema[NUM_EXPERTS];
#pragma unroll
        for (int e = 0; e < NUM_EXPERTS; e++) {
            ema[e] = (1.0f - ALPHA) * usage_ema[e] + ALPHA * mask[e];
            float dd = ema[e] - target;
            acc += dd * dd;
        }
        float balance_loss = (acc / NUM_EXPERTS) * Z_LOSS;

        // output layout: mask[16], probs[16], loss[1], ema[16], topk_idx[2]
        int o = 0;
#pragma unroll
        for (int e = 0; e < NUM_EXPERTS; e++) out[o++] = mask[e];
#pragma unroll
        for (int e = 0; e < NUM_EXPERTS; e++) out[o++] = probs[e];
        out[o++] = balance_loss;
#pragma unroll
        for (int e = 0; e < NUM_EXPERTS; e++) out[o++] = ema[e];
        out[o++] = (float)i0;
        out[o++] = (float)i1;

        g_ticket = 0;   // reset for next graph replay
    }
}

extern "C" void kernel_launch(void* const* d_in, const int* in_sizes, int n_in,
                              void* d_out, int out_size) {
    const char*  wm        = (const char*)d_in[0];
    const float* protos    = (const float*)d_in[1];
    const float* usage_ema = (const float*)d_in[2];
    float* out = (float*)d_out;

    const int n = in_sizes[0];  // 33554432
    router_kernel<<<GRID, NTHREADS, SMEM_BYTES>>>(wm, protos, usage_ema,
                                                  out, out_size, 1.0f / (float)n);
}

// round 11
// speedup vs baseline: 1.3373x; 1.3373x over previous
#include <cuda_runtime.h>
#include <cuda_bf16.h>

#define NUM_EXPERTS 16
#define Z_LOSS 1e-3f
#define ALPHA (1.0f / 1000.0f)

#define R_BLOCKS 1216            // 152 SMs * 8 blocks -> exactly one balanced wave
#define R_THREADS 256
#define N4_TOTAL 8388608u        // 4*4096*2048 floats / 4
#define R_STRIDE (R_BLOCKS * R_THREADS)   // 311296
#define FULL_ITERS 26u           // 26*311296 = 8093696; remainder 294912 predicated

__device__ float g_partials[R_BLOCKS];
__device__ int g_ticket = 0;   // reset to 0 by the last block each launch

__global__ __launch_bounds__(R_THREADS, 8) void router_kernel(
    const float4* __restrict__ x,
    const float* __restrict__ prototypes,
    const float* __restrict__ usage_ema,
    float* __restrict__ out, int out_size, float inv_n)
{
    __shared__ float sdata[R_THREADS / 32];
    __shared__ bool is_last;
    const int tid = threadIdx.x;

    // ---- phase 1: single balanced wave, coalesced grid-stride stream ----
    const unsigned gid = blockIdx.x * R_THREADS + tid;

    float s0 = 0.f, s1 = 0.f, s2 = 0.f, s3 = 0.f;
#pragma unroll
    for (unsigned i = 0; i < FULL_ITERS; i++) {
        float4 v = x[gid + i * R_STRIDE];
        s0 += v.x; s1 += v.y; s2 += v.z; s3 += v.w;
    }
    {
        unsigned idx = gid + FULL_ITERS * R_STRIDE;
        if (idx < N4_TOTAL) {
            float4 v = x[idx];
            s0 += v.x; s1 += v.y; s2 += v.z; s3 += v.w;
        }
    }
    float s = (s0 + s1) + (s2 + s3);

#pragma unroll
    for (int off = 16; off > 0; off >>= 1)
        s += __shfl_down_sync(0xffffffffu, s, off);

    if ((tid & 31) == 0) sdata[tid >> 5] = s;
    __syncthreads();
    if (tid < 32) {
        float v = (tid < R_THREADS / 32) ? sdata[tid] : 0.f;
#pragma unroll
        for (int off = 4; off > 0; off >>= 1)
            v += __shfl_down_sync(0xffffffffu, v, off);
        if (tid == 0) {
            g_partials[blockIdx.x] = v;
            __threadfence();
            int old = atomicAdd(&g_ticket, 1);
            is_last = (old == R_BLOCKS - 1);
        }
    }
    __syncthreads();
    if (!is_last) return;

    // ---- phase 2 (last block only): reduce 1216 partials ----
    float t = 0.f;
#pragma unroll
    for (int i = 0; i < (R_BLOCKS + R_THREADS - 1) / R_THREADS; i++) {
        int idx = tid + i * R_THREADS;
        if (idx < R_BLOCKS) t += __ldcg(&g_partials[idx]);
    }
#pragma unroll
    for (int off = 16; off > 0; off >>= 1)
        t += __shfl_down_sync(0xffffffffu, t, off);
    if ((tid & 31) == 0) sdata[tid >> 5] = t;

    // initialize every output element (d_out is poisoned with 0xAA)
    for (int i = tid; i < out_size; i += R_THREADS) out[i] = 0.0f;
    __syncthreads();

    if (tid == 0) {
        float tot = 0.f;
#pragma unroll
        for (int i = 0; i < R_THREADS / 32; i++) tot += sdata[i];
        float xm = tot * inv_n;

        // sim = -(p_e - x)^2 ; softmax
        float sim[NUM_EXPERTS];
        float mx = -3.4e38f;
#pragma unroll
        for (int e = 0; e < NUM_EXPERTS; e++) {
            float dd = prototypes[e] - xm;
            sim[e] = -dd * dd;
            if (sim[e] > mx) mx = sim[e];
        }
        float probs[NUM_EXPERTS];
        float denom = 0.f;
#pragma unroll
        for (int e = 0; e < NUM_EXPERTS; e++) {
            probs[e] = expf(sim[e] - mx);
            denom += probs[e];
        }
        float inv_denom = 1.0f / denom;
#pragma unroll
        for (int e = 0; e < NUM_EXPERTS; e++) probs[e] *= inv_denom;

        // stable top-2 (ties -> lowest index, matching jax.lax.top_k)
        int i0 = 0;
        for (int e = 1; e < NUM_EXPERTS; e++)
            if (probs[e] > probs[i0]) i0 = e;
        int i1 = (i0 == 0) ? 1 : 0;
        for (int e = 0; e < NUM_EXPERTS; e++) {
            if (e == i0) continue;
            if (probs[e] > probs[i1]) i1 = e;
        }

        float mask[NUM_EXPERTS];
#pragma unroll
        for (int e = 0; e < NUM_EXPERTS; e++) mask[e] = 0.f;
        mask[i0] = 1.f; mask[i1] = 1.f;

        const float target = 1.0f / NUM_EXPERTS;
        float acc = 0.f;
        float ema[NUM_EXPERTS];
#pragma unroll
        for (int e = 0; e < NUM_EXPERTS; e++) {
            ema[e] = (1.0f - ALPHA) * usage_ema[e] + ALPHA * mask[e];
            float dd = ema[e] - target;
            acc += dd * dd;
        }
        float balance_loss = (acc / NUM_EXPERTS) * Z_LOSS;

        // output layout: mask[16], probs[16], loss[1], ema[16], topk_idx[2]
        int o = 0;
#pragma unroll
        for (int e = 0; e < NUM_EXPERTS; e++) out[o++] = mask[e];
#pragma unroll
        for (int e = 0; e < NUM_EXPERTS; e++) out[o++] = probs[e];
        out[o++] = balance_loss;
#pragma unroll
        for (int e = 0; e < NUM_EXPERTS; e++) out[o++] = ema[e];
        out[o++] = (float)i0;
        out[o++] = (float)i1;

        // reset ticket for the next graph replay
        g_ticket = 0;
    }
}

extern "C" void kernel_launch(void* const* d_in, const int* in_sizes, int n_in,
                              void* d_out, int out_size) {
    const float* wm        = (const float*)d_in[0];
    const float* protos    = (const float*)d_in[1];
    const float* usage_ema = (const float*)d_in[2];
    float* out = (float*)d_out;

    const int n = in_sizes[0];  // 33554432
    router_kernel<<<R_BLOCKS, R_THREADS>>>((const float4*)wm, protos, usage_ema,
                                           out, out_size, 1.0f / (float)n);
}

// round 12
// speedup vs baseline: 1.3388x; 1.0012x over previous
#include <cuda_runtime.h>
#include <cuda_bf16.h>
#include <cstdint>

#define NUM_EXPERTS 16
#define Z_LOSS 1e-3f
#define ALPHA (1.0f / 1000.0f)

#define R_BLOCKS 1216            // 152 SMs * 8 blocks -> exactly one balanced wave
#define R_THREADS 256
#define N4_TOTAL 8388608u        // 4*4096*2048 floats / 4
#define R_STRIDE (R_BLOCKS * R_THREADS)   // 311296
#define FULL_ITERS 26u           // 26*311296 = 8093696; remainder 294912 predicated

__device__ float g_partials[R_BLOCKS];
__device__ int g_ticket = 0;   // reset to 0 by the last block each launch

__global__ __launch_bounds__(R_THREADS, 8) void router_kernel(
    const float4* __restrict__ x,
    const float* __restrict__ prototypes,
    const float* __restrict__ usage_ema,
    float* __restrict__ out, int out_size, float inv_n)
{
    __shared__ float sdata[R_THREADS / 32];
    __shared__ float sh_xm;
    __shared__ bool is_last;
    const int tid = threadIdx.x;

    // keep the tiny tail inputs L2-resident across the stream
    if (tid == 0) {
        asm volatile("prefetch.global.L2 [%0];" :: "l"(prototypes));
        asm volatile("prefetch.global.L2 [%0];" :: "l"(usage_ema));
    }

    // ---- phase 1: single balanced wave, coalesced evict-first stream ----
    const unsigned gid = blockIdx.x * R_THREADS + tid;

    float s0 = 0.f, s1 = 0.f, s2 = 0.f, s3 = 0.f;
#pragma unroll
    for (unsigned i = 0; i < FULL_ITERS; i++) {
        float4 v = __ldcs(&x[gid + i * R_STRIDE]);
        s0 += v.x; s1 += v.y; s2 += v.z; s3 += v.w;
    }
    {
        unsigned idx = gid + FULL_ITERS * R_STRIDE;
        if (idx < N4_TOTAL) {
            float4 v = __ldcs(&x[idx]);
            s0 += v.x; s1 += v.y; s2 += v.z; s3 += v.w;
        }
    }
    float s = (s0 + s1) + (s2 + s3);

#pragma unroll
    for (int off = 16; off > 0; off >>= 1)
        s += __shfl_down_sync(0xffffffffu, s, off);

    if ((tid & 31) == 0) sdata[tid >> 5] = s;
    __syncthreads();
    if (tid < 32) {
        float v = (tid < R_THREADS / 32) ? sdata[tid] : 0.f;
#pragma unroll
        for (int off = 4; off > 0; off >>= 1)
            v += __shfl_down_sync(0xffffffffu, v, off);
        if (tid == 0) {
            g_partials[blockIdx.x] = v;
            __threadfence();
            int old = atomicAdd(&g_ticket, 1);
            is_last = (old == R_BLOCKS - 1);
        }
    }
    __syncthreads();
    if (!is_last) return;

    // ---- phase 2 (last block only): reduce 1216 partials ----
    float t = 0.f;
#pragma unroll
    for (int i = 0; i < (R_BLOCKS + R_THREADS - 1) / R_THREADS; i++) {
        int idx = tid + i * R_THREADS;
        if (idx < R_BLOCKS) t += __ldcg(&g_partials[idx]);
    }
#pragma unroll
    for (int off = 16; off > 0; off >>= 1)
        t += __shfl_down_sync(0xffffffffu, t, off);
    if ((tid & 31) == 0) sdata[tid >> 5] = t;

    // initialize every output element (d_out is poisoned with 0xAA)
    for (int i = tid; i < out_size; i += R_THREADS) out[i] = 0.0f;
    __syncthreads();

    if (tid == 0) {
        float tot = 0.f;
#pragma unroll
        for (int i = 0; i < R_THREADS / 32; i++) tot += sdata[i];
        sh_xm = tot * inv_n;
    }
    __syncthreads();

    // ---- warp-parallel epilogue: lane e owns expert e (lanes 16-31 inert) ----
    if (tid < 32) {
        const unsigned FULL = 0xffffffffu;
        const int lane = tid;
        const bool act = (lane < NUM_EXPERTS);
        const float xm = sh_xm;

        float sim = -3.4e38f;
        if (act) {
            float dd = prototypes[lane] - xm;
            sim = -dd * dd;
        }
        // max over all lanes (inert lanes hold -inf-ish)
        float mx = sim;
#pragma unroll
        for (int off = 16; off > 0; off >>= 1)
            mx = fmaxf(mx, __shfl_xor_sync(FULL, mx, off));

        float ex = act ? expf(sim - mx) : 0.f;
        float denom = ex;
#pragma unroll
        for (int off = 16; off > 0; off >>= 1)
            denom += __shfl_xor_sync(FULL, denom, off);
        float prob = act ? (ex / denom) : -1.f;

        // top-1 with lowest-index tie-break
        float bv = prob; int bi = lane;
#pragma unroll
        for (int off = 16; off > 0; off >>= 1) {
            float ov = __shfl_xor_sync(FULL, bv, off);
            int   oi = __shfl_xor_sync(FULL, bi, off);
            if (ov > bv || (ov == bv && oi < bi)) { bv = ov; bi = oi; }
        }
        const int i0 = bi;

        // top-2: exclude i0
        float v2 = (act && lane != i0) ? prob : -1.f;
        float bv2 = v2; int bi2 = lane;
#pragma unroll
        for (int off = 16; off > 0; off >>= 1) {
            float ov = __shfl_xor_sync(FULL, bv2, off);
            int   oi = __shfl_xor_sync(FULL, bi2, off);
            if (ov > bv2 || (ov == bv2 && oi < bi2)) { bv2 = ov; bi2 = oi; }
        }
        const int i1 = bi2;

        float mask = (lane == i0 || lane == i1) ? 1.f : 0.f;
        float ema = 0.f, sq = 0.f;
        if (act) {
            ema = (1.0f - ALPHA) * usage_ema[lane] + ALPHA * mask;
            float dd = ema - (1.0f / NUM_EXPERTS);
            sq = dd * dd;
        }
        float acc = sq;
#pragma unroll
        for (int off = 16; off > 0; off >>= 1)
            acc += __shfl_xor_sync(FULL, acc, off);

        // output layout: mask[16], probs[16], loss[1], ema[16], topk_idx[2]
        if (act) {
            out[lane] = mask;
            out[NUM_EXPERTS + lane] = prob;
            out[2 * NUM_EXPERTS + 1 + lane] = ema;
        }
        if (lane == 0) {
            out[2 * NUM_EXPERTS] = (acc / NUM_EXPERTS) * Z_LOSS;
            out[3 * NUM_EXPERTS + 1] = (float)i0;
            out[3 * NUM_EXPERTS + 2] = (float)i1;
            g_ticket = 0;   // reset for next graph replay
        }
    }
}

extern "C" void kernel_launch(void* const* d_in, const int* in_sizes, int n_in,
                              void* d_out, int out_size) {
    const float* wm        = (const float*)d_in[0];
    const float* protos    = (const float*)d_in[1];
    const float* usage_ema = (const float*)d_in[2];
    float* out = (float*)d_out;

    const int n = in_sizes[0];  // 33554432
    router_kernel<<<R_BLOCKS, R_THREADS>>>((const float4*)wm, protos, usage_ema,
                                           out, out_size, 1.0f / (float)n);
}